// round 2
// baseline (speedup 1.0000x reference)
#include <cuda_runtime.h>
#include <math.h>
#include <stdint.h>

// Problem constants: B=16, SEG=512, MEM=512, TOTAL=1024, MD=128, H=8, D=128

// ---------------- scratch (static __device__ arrays; sanctioned) ----------------
__device__ float g_h   [16 * 1024 * 128];          // concat(mem,x)      8 MB
__device__ float g_qf  [16 * 512 * 1024];          // x@Wq              32 MB
__device__ float g_kvf [16 * 1024 * 2048];         // h@Wkv            128 MB
__device__ float g_rf  [1024 * 1024];              // R@Wr               4 MB
__device__ float g_s   [128ll * 512 * 1024];       // scores/probs     256 MB
__device__ float g_att [16 * 512 * 1024];          // attention out     32 MB
__device__ float g_y   [16 * 512 * 128];           // pre-LN y           4 MB

// ---------------- concat(mem, x) -> g_h ----------------
__global__ __launch_bounds__(256) void concat_kernel(
    const float* __restrict__ x, const float* __restrict__ mem, float* __restrict__ hout)
{
    long idx = (long)blockIdx.x * blockDim.x + threadIdx.x;   // float4 index
    long e = idx * 4;                                         // element index < 2,097,152
    int b   = (int)(e >> 17);       // 1024*128 per batch
    int rem = (int)(e & 131071);
    float4 v;
    if (rem < 65536)  v = *(const float4*)(mem + (long)b * 65536 + rem);
    else              v = *(const float4*)(x   + (long)b * 65536 + rem - 65536);
    *(float4*)(hout + e) = v;
}

// ---------------- generic batched NN GEMM: C = A(MxK) @ B(KxN) [+resid] ----------------
__global__ __launch_bounds__(256) void gemm_nn(
    const float* __restrict__ Ab, const float* __restrict__ Bb, float* __restrict__ Cb,
    int M, int N, int K, long sA, long sB, long sC, const float* __restrict__ resid)
{
    const float* A  = Ab + (long)blockIdx.z * sA;
    const float* Bm = Bb + (long)blockIdx.z * sB;
    float*       C  = Cb + (long)blockIdx.z * sC;

    __shared__ __align__(16) float As[16][64];
    __shared__ __align__(16) float Bs[16][64];

    const int tid = threadIdx.x;
    const int tx = tid & 15, ty = tid >> 4;
    const int m0 = blockIdx.y << 6, n0 = blockIdx.x << 6;
    const int ar = tid >> 2,  ac = (tid & 3)  << 2;   // A tile 64x16
    const int br = tid >> 4,  bc = (tid & 15) << 2;   // B tile 16x64

    float acc[4][4] = {};

    const float* Aptr = A  + (long)(m0 + ar) * K + ac;
    const float* Bptr = Bm + (long)br * N + n0 + bc;

    for (int k0 = 0; k0 < K; k0 += 16) {
        float4 av = *(const float4*)(Aptr + k0);
        float4 bv = *(const float4*)(Bptr + (long)k0 * N);
        __syncthreads();
        As[ac + 0][ar] = av.x; As[ac + 1][ar] = av.y;
        As[ac + 2][ar] = av.z; As[ac + 3][ar] = av.w;
        *(float4*)&Bs[br][bc] = bv;
        __syncthreads();
#pragma unroll
        for (int kk = 0; kk < 16; kk++) {
            float4 a = *(const float4*)&As[kk][ty << 2];
            float4 b = *(const float4*)&Bs[kk][tx << 2];
            acc[0][0] += a.x * b.x; acc[0][1] += a.x * b.y; acc[0][2] += a.x * b.z; acc[0][3] += a.x * b.w;
            acc[1][0] += a.y * b.x; acc[1][1] += a.y * b.y; acc[1][2] += a.y * b.z; acc[1][3] += a.y * b.w;
            acc[2][0] += a.z * b.x; acc[2][1] += a.z * b.y; acc[2][2] += a.z * b.z; acc[2][3] += a.z * b.w;
            acc[3][0] += a.w * b.x; acc[3][1] += a.w * b.y; acc[3][2] += a.w * b.z; acc[3][3] += a.w * b.w;
        }
    }
#pragma unroll
    for (int ii = 0; ii < 4; ii++) {
        int row = m0 + (ty << 2) + ii;
        long rb = (long)row * N + n0 + (tx << 2);
        float4 v = make_float4(acc[ii][0], acc[ii][1], acc[ii][2], acc[ii][3]);
        if (resid) {
            float4 r4 = *(const float4*)(resid + rb);
            v.x += r4.x; v.y += r4.y; v.z += r4.z; v.w += r4.w;
        }
        *(float4*)(C + rb) = v;
    }
}

// ---------------- fused attention score kernel ----------------
// S[i][j] = ( (q_i+u1)·k_j + (q_i+u2)·r_{511+j-i} ) / sqrt(128)   for j <= i+512
// Per 64x64 tile, the circulant index c = 511+j-i spans 127 consecutive rows of r,
// staged in smem transposed as Rs[kk][co], co = c - cbase, cbase = 448 + j0 - i0.
__global__ __launch_bounds__(256) void score_kernel(
    const float* __restrict__ Qb, const float* __restrict__ Kb,
    const float* __restrict__ Rf,
    const float* __restrict__ U1, const float* __restrict__ U2,
    float* __restrict__ Sb)
{
    if (blockIdx.x > blockIdx.y + 8) return;           // fully masked tile
    const int z  = blockIdx.z;
    const int i0 = blockIdx.y << 6, j0 = blockIdx.x << 6;
    const int h  = z & 7;

    const float* Q  = Qb + (long)z * 65536;
    const float* K  = Kb + (long)z * 131072;
    const float* Rh = Rf + (long)h * 131072;
    const float* u1 = U1 + (h << 7);
    const float* u2 = U2 + (h << 7);
    float*       S  = Sb + (long)z * 524288;

    __shared__ __align__(16) float As[16][64];     // [kk][m]  (q, raw)
    __shared__ __align__(16) float Bs[16][64];     // [kk][n]  (k)
    __shared__ __align__(16) float Rs[16][128];    // [kk][co] (r band)
    __shared__ float u1s[16], u2s[16];

    const int tid = threadIdx.x;
    const int tx = tid & 15, ty = tid >> 4;
    const int r = tid >> 2,  c = (tid & 3) << 2;   // A/B load: row r, col c
    const int rr = tid >> 1, rc = (tid & 1) << 3;  // R load: row rr (0..127), cols rc..rc+7
    const int cbase = 448 + j0 - i0;               // >= 0 always
    int crow = cbase + rr; if (crow > 1023) crow = 1023;  // clamp (values unused)
    const int rbase = 60 + ((tx - ty) << 2);       // in [0,120], 16B-aligned

    float aac[4][4] = {};
    float abd[4][4] = {};

#pragma unroll
    for (int k0 = 0; k0 < 128; k0 += 16) {
        float4 av  = *(const float4*)(Q  + (long)(i0 + r) * 128 + k0 + c);
        float4 bv  = *(const float4*)(K  + (long)(j0 + r) * 128 + k0 + c);
        float4 rv0 = *(const float4*)(Rh + (long)crow * 128 + k0 + rc);
        float4 rv1 = *(const float4*)(Rh + (long)crow * 128 + k0 + rc + 4);
        __syncthreads();
        As[c + 0][r] = av.x; As[c + 1][r] = av.y; As[c + 2][r] = av.z; As[c + 3][r] = av.w;
        Bs[c + 0][r] = bv.x; Bs[c + 1][r] = bv.y; Bs[c + 2][r] = bv.z; Bs[c + 3][r] = bv.w;
        Rs[rc + 0][rr] = rv0.x; Rs[rc + 1][rr] = rv0.y; Rs[rc + 2][rr] = rv0.z; Rs[rc + 3][rr] = rv0.w;
        Rs[rc + 4][rr] = rv1.x; Rs[rc + 5][rr] = rv1.y; Rs[rc + 6][rr] = rv1.z; Rs[rc + 7][rr] = rv1.w;
        if (tid < 16) { u1s[tid] = u1[k0 + tid]; u2s[tid] = u2[k0 + tid]; }
        __syncthreads();
#pragma unroll
        for (int kk = 0; kk < 16; kk++) {
            float4 a = *(const float4*)&As[kk][ty << 2];
            float4 b = *(const float4*)&Bs[kk][tx << 2];
            float u1k = u1s[kk], u2k = u2s[kk];
            float a1[4] = {a.x + u1k, a.y + u1k, a.z + u1k, a.w + u1k};
            float a2[4] = {a.x + u2k, a.y + u2k, a.z + u2k, a.w + u2k};
            // AC part
#pragma unroll
            for (int ii = 0; ii < 4; ii++) {
                aac[ii][0] += a1[ii] * b.x; aac[ii][1] += a1[ii] * b.y;
                aac[ii][2] += a1[ii] * b.z; aac[ii][3] += a1[ii] * b.w;
            }
            // BD part: r values for co = rbase+3 + (jj-ii), need indices rbase..rbase+6
            float4 r0 = *(const float4*)&Rs[kk][rbase];
            float4 r1 = *(const float4*)&Rs[kk][rbase + 4];
            float rv[8] = {r0.x, r0.y, r0.z, r0.w, r1.x, r1.y, r1.z, r1.w};
#pragma unroll
            for (int ii = 0; ii < 4; ii++) {
#pragma unroll
                for (int jj = 0; jj < 4; jj++) {
                    abd[ii][jj] += a2[ii] * rv[jj - ii + 3];
                }
            }
        }
    }

    const float inv = 0.08838834764831845f;   // 1/sqrt(128)
#pragma unroll
    for (int ii = 0; ii < 4; ii++) {
        int i  = i0 + (ty << 2) + ii;
        int jb = j0 + (tx << 2);
#pragma unroll
        for (int jj = 0; jj < 4; jj++) {
            int j = jb + jj;
            if (j <= i + 512) {
                S[(long)i * 1024 + j] = (aac[ii][jj] + abd[ii][jj]) * inv;
            }
        }
    }
}

// ---------------- causal softmax over rows of g_s (valid width = i+513) ----------------
__global__ __launch_bounds__(256) void softmax_kernel(float* __restrict__ S)
{
    const int row  = (blockIdx.x << 3) + (threadIdx.x >> 5);
    const int lane = threadIdx.x & 31;
    const int i = row & 511;
    const int valid = i + 513;
    float* p = S + (long)row * 1024;

    float4 v[8];
    float mx = -3.402823466e38f;
#pragma unroll
    for (int c2 = 0; c2 < 8; c2++) {
        int jb = (c2 << 7) + (lane << 2);
        v[c2] = *(const float4*)(p + jb);
        if (jb + 0 < valid) mx = fmaxf(mx, v[c2].x);
        if (jb + 1 < valid) mx = fmaxf(mx, v[c2].y);
        if (jb + 2 < valid) mx = fmaxf(mx, v[c2].z);
        if (jb + 3 < valid) mx = fmaxf(mx, v[c2].w);
    }
#pragma unroll
    for (int o = 16; o > 0; o >>= 1) mx = fmaxf(mx, __shfl_xor_sync(0xffffffffu, mx, o));

    float sum = 0.f;
#pragma unroll
    for (int c2 = 0; c2 < 8; c2++) {
        int jb = (c2 << 7) + (lane << 2);
        float e0 = (jb + 0 < valid) ? __expf(v[c2].x - mx) : 0.f;
        float e1 = (jb + 1 < valid) ? __expf(v[c2].y - mx) : 0.f;
        float e2 = (jb + 2 < valid) ? __expf(v[c2].z - mx) : 0.f;
        float e3 = (jb + 3 < valid) ? __expf(v[c2].w - mx) : 0.f;
        v[c2].x = e0; v[c2].y = e1; v[c2].z = e2; v[c2].w = e3;
        sum += e0 + e1 + e2 + e3;
    }
#pragma unroll
    for (int o = 16; o > 0; o >>= 1) sum += __shfl_xor_sync(0xffffffffu, sum, o);
    float rs = 1.0f / sum;
#pragma unroll
    for (int c2 = 0; c2 < 8; c2++) {
        int jb = (c2 << 7) + (lane << 2);
        v[c2].x *= rs; v[c2].y *= rs; v[c2].z *= rs; v[c2].w *= rs;
        *(float4*)(p + jb) = v[c2];
    }
}

// ---------------- LayerNorm over last dim (128) ----------------
__global__ __launch_bounds__(256) void ln_kernel(
    const float* __restrict__ Y, const float* __restrict__ gamma,
    const float* __restrict__ beta, float* __restrict__ out)
{
    const int row  = (blockIdx.x << 3) + (threadIdx.x >> 5);
    const int lane = threadIdx.x & 31;
    const float* y = Y + (long)row * 128;

    float4 v = *(const float4*)(y + (lane << 2));
    float s = v.x + v.y + v.z + v.w;
#pragma unroll
    for (int o = 16; o > 0; o >>= 1) s += __shfl_xor_sync(0xffffffffu, s, o);
    float mu = s * (1.0f / 128.0f);

    float dx = v.x - mu, dy = v.y - mu, dz = v.z - mu, dw = v.w - mu;
    float q = dx * dx + dy * dy + dz * dz + dw * dw;
#pragma unroll
    for (int o = 16; o > 0; o >>= 1) q += __shfl_xor_sync(0xffffffffu, q, o);
    float inv = rsqrtf(q * (1.0f / 128.0f) + 1e-5f);

    float4 g  = *(const float4*)(gamma + (lane << 2));
    float4 b4 = *(const float4*)(beta + (lane << 2));
    float4 o4;
    o4.x = dx * inv * g.x + b4.x;
    o4.y = dy * inv * g.y + b4.y;
    o4.z = dz * inv * g.z + b4.z;
    o4.w = dw * inv * g.w + b4.w;
    *(float4*)(out + (long)row * 128 + (lane << 2)) = o4;
}

// ---------------- launch ----------------
extern "C" void kernel_launch(void* const* d_in, const int* in_sizes, int n_in,
                              void* d_out, int out_size)
{
    const float* x     = (const float*)d_in[0];
    const float* mem   = (const float*)d_in[1];
    const float* R     = (const float*)d_in[2];
    // d_in[3] = att_mask (all ones; unused by reference)
    const float* u1    = (const float*)d_in[4];
    const float* u2    = (const float*)d_in[5];
    const float* Wq    = (const float*)d_in[6];
    const float* Wkv   = (const float*)d_in[7];
    const float* Wr    = (const float*)d_in[8];
    const float* Wmlp  = (const float*)d_in[9];
    const float* gamma = (const float*)d_in[10];
    const float* beta  = (const float*)d_in[11];
    float* out = (float*)d_out;

    float *hb, *qf, *kvf, *rf, *sb, *att, *yb;
    cudaGetSymbolAddress((void**)&hb,  g_h);
    cudaGetSymbolAddress((void**)&qf,  g_qf);
    cudaGetSymbolAddress((void**)&kvf, g_kvf);
    cudaGetSymbolAddress((void**)&rf,  g_rf);
    cudaGetSymbolAddress((void**)&sb,  g_s);
    cudaGetSymbolAddress((void**)&att, g_att);
    cudaGetSymbolAddress((void**)&yb,  g_y);

    // 1) h = concat(mem, x)
    concat_kernel<<<2048, 256>>>(x, mem, hb);
    // 2) qf = x @ Wq           (8192 x 1024, K=128)
    gemm_nn<<<dim3(16, 128, 1), 256>>>(x, Wq, qf, 8192, 1024, 128, 0, 0, 0, nullptr);
    // 3) kvf = h @ Wkv         (16384 x 2048, K=128)
    gemm_nn<<<dim3(32, 256, 1), 256>>>(hb, Wkv, kvf, 16384, 2048, 128, 0, 0, 0, nullptr);
    // 4) rf = R @ Wr           (1024 x 1024, K=128)
    gemm_nn<<<dim3(16, 16, 1), 256>>>(R, Wr, rf, 1024, 1024, 128, 0, 0, 0, nullptr);
    // 5) S = ((q+u1)@k^T + circulant((q+u2)@r^T)) / sqrt(d), causal band only
    score_kernel<<<dim3(16, 8, 128), 256>>>(qf, kvf, rf, u1, u2, sb);
    // 6) P = softmax(S) with analytic causal mask (zeros outside)
    softmax_kernel<<<8192, 256>>>(sb);
    // 7) att = P @ V           per (b,h): 512 x 128, K=1024  (V = second half of kvf)
    gemm_nn<<<dim3(2, 8, 128), 256>>>(sb, kvf + 16777216L, att,
                                      512, 128, 1024, 524288L, 131072L, 65536L, nullptr);
    // 8) y = att @ Wmlp + x    (8192 x 128, K=1024)
    gemm_nn<<<dim3(2, 128, 1), 256>>>(att, Wmlp, yb, 8192, 128, 1024, 0, 0, 0, x);
    // 9) out = LayerNorm(y) * gamma + beta
    ln_kernel<<<1024, 256>>>(yb, gamma, beta, out);
}

// round 3
// speedup vs baseline: 2.3775x; 2.3775x over previous
#include <cuda_runtime.h>
#include <math.h>
#include <stdint.h>

// Problem constants: B=16, SEG=512, MEM=512, TOTAL=1024, MD=128, H=8, D=128

// ---------------- scratch ----------------
__device__ float g_h   [16 * 1024 * 128];          // concat(mem,x)      8 MB
__device__ float g_qf  [16 * 512 * 1024];          // x@Wq              32 MB
__device__ float g_kvf [16 * 1024 * 2048];         // h@Wkv            128 MB
__device__ float g_rf  [1024 * 1024];              // R@Wr               4 MB
__device__ float g_s   [128ll * 512 * 1024];       // scores/probs     256 MB
__device__ float g_att [16 * 512 * 1024];          // attention out     32 MB
__device__ float g_y   [16 * 512 * 128];           // pre-LN y           4 MB

// ---------------- tf32 helpers ----------------
__device__ __forceinline__ uint32_t f2tf(float f) {
    uint32_t u; asm("cvt.rna.tf32.f32 %0, %1;" : "=r"(u) : "f"(f)); return u;
}
__device__ __forceinline__ uint4 cvt4(float4 v) {
    return make_uint4(f2tf(v.x), f2tf(v.y), f2tf(v.z), f2tf(v.w));
}
__device__ __forceinline__ void mma8(float4& c, const uint32_t a[4], uint32_t b0, uint32_t b1) {
    asm volatile("mma.sync.aligned.m16n8k8.row.col.f32.tf32.tf32.f32 "
        "{%0,%1,%2,%3}, {%4,%5,%6,%7}, {%8,%9}, {%0,%1,%2,%3};"
        : "+f"(c.x), "+f"(c.y), "+f"(c.z), "+f"(c.w)
        : "r"(a[0]), "r"(a[1]), "r"(a[2]), "r"(a[3]), "r"(b0), "r"(b1));
}

// ---------------- concat(mem, x) -> g_h ----------------
__global__ __launch_bounds__(256) void concat_kernel(
    const float* __restrict__ x, const float* __restrict__ mem, float* __restrict__ hout)
{
    long idx = (long)blockIdx.x * blockDim.x + threadIdx.x;
    long e = idx * 4;
    int b   = (int)(e >> 17);
    int rem = (int)(e & 131071);
    float4 v;
    if (rem < 65536)  v = *(const float4*)(mem + (long)b * 65536 + rem);
    else              v = *(const float4*)(x   + (long)b * 65536 + rem - 65536);
    *(float4*)(hout + e) = v;
}

// ---------------- tf32 NN GEMM: C = A(MxK) @ B(KxN) [+resid], batched ----------------
// Block tile 128x128, BK=32, 256 threads, 8 warps (warp tile 64x32).
// M % 128 == 0, N % 128 == 0, K % 32 == 0 (all shapes here satisfy this).
__global__ __launch_bounds__(256) void gemm_tf32(
    const float* __restrict__ Ab, const float* __restrict__ Bb, float* __restrict__ Cb,
    int M, int N, int K, long sA, long sB, long sC, const float* __restrict__ resid)
{
    const float* A = Ab + (long)blockIdx.z * sA;
    const float* B = Bb + (long)blockIdx.z * sB;
    float*       C = Cb + (long)blockIdx.z * sC;

    __shared__ __align__(16) uint32_t As[128 * 36];   // [m][k], tf32
    __shared__ __align__(16) uint32_t Bs[32 * 132];   // [k][n], tf32

    const int tid = threadIdx.x, lane = tid & 31, wid = tid >> 5;
    const int m0 = blockIdx.y << 7, n0 = blockIdx.x << 7;
    const int wm = (wid & 1) << 6;          // 0/64
    const int wn = (wid >> 1) << 5;         // 0/32/64/96
    const int g = lane >> 2, lt = lane & 3;

    const int am = tid >> 3, ak = (tid & 7) << 2;     // A: 32 rows/pass, 4 passes
    const int bk = tid >> 5, bn = (tid & 31) << 2;    // B: 8 k-rows/pass, 4 passes

    float4 acc[4][4];
#pragma unroll
    for (int t = 0; t < 4; t++)
#pragma unroll
        for (int s = 0; s < 4; s++) acc[t][s] = make_float4(0.f, 0.f, 0.f, 0.f);

    for (int k0 = 0; k0 < K; k0 += 32) {
        uint4 ta[4], tb[4];
#pragma unroll
        for (int it = 0; it < 4; it++) {
            ta[it] = cvt4(*(const float4*)(A + (long)(m0 + am + (it << 5)) * K + k0 + ak));
            tb[it] = cvt4(*(const float4*)(B + (long)(k0 + bk + (it << 3)) * N + n0 + bn));
        }
        __syncthreads();
#pragma unroll
        for (int it = 0; it < 4; it++) {
            *(uint4*)&As[(am + (it << 5)) * 36 + ak] = ta[it];
            *(uint4*)&Bs[(bk + (it << 3)) * 132 + bn] = tb[it];
        }
        __syncthreads();
#pragma unroll
        for (int kk = 0; kk < 4; kk++) {
            const int kb = kk << 3;
            uint32_t af[4][4];
#pragma unroll
            for (int t = 0; t < 4; t++) {
                int row = wm + (t << 4) + g;
                af[t][0] = As[row * 36 + kb + lt];
                af[t][1] = As[(row + 8) * 36 + kb + lt];
                af[t][2] = As[row * 36 + kb + lt + 4];
                af[t][3] = As[(row + 8) * 36 + kb + lt + 4];
            }
#pragma unroll
            for (int s = 0; s < 4; s++) {
                int col = wn + (s << 3) + g;
                uint32_t b0 = Bs[(kb + lt) * 132 + col];
                uint32_t b1 = Bs[(kb + lt + 4) * 132 + col];
#pragma unroll
                for (int t = 0; t < 4; t++) mma8(acc[t][s], af[t], b0, b1);
            }
        }
    }

#pragma unroll
    for (int t = 0; t < 4; t++) {
        int r0 = m0 + wm + (t << 4) + g;
#pragma unroll
        for (int s = 0; s < 4; s++) {
            int c = n0 + wn + (s << 3) + (lt << 1);
            float2 v0 = make_float2(acc[t][s].x, acc[t][s].y);
            float2 v1 = make_float2(acc[t][s].z, acc[t][s].w);
            if (resid) {
                float2 r4 = *(const float2*)(resid + (long)r0 * N + c);
                v0.x += r4.x; v0.y += r4.y;
                float2 r5 = *(const float2*)(resid + (long)(r0 + 8) * N + c);
                v1.x += r5.x; v1.y += r5.y;
            }
            *(float2*)(C + (long)r0 * N + c) = v0;
            *(float2*)(C + (long)(r0 + 8) * N + c) = v1;
        }
    }
}

// ---------------- fused tf32 score kernel ----------------
// S[i][j] = ((q_i+u1)·k_j + (q_i+u2)·r_{511+j-i}) / sqrt(128), j <= i+512.
// 64x64 output tile, 256 threads, 8 warps: warp = (wm in 0..3: 16 rows) x (half: AC 32 cols, BD 64 cols).
// BD computed as a 64x128 mma panel into smem (banded r), then diagonally gathered.
__global__ __launch_bounds__(256) void score_tf32(
    const float* __restrict__ Qb, const float* __restrict__ Kb,
    const float* __restrict__ Rf, const float* __restrict__ U1,
    const float* __restrict__ U2, float* __restrict__ Sb)
{
    if (blockIdx.x > blockIdx.y + 8) return;           // fully masked tile
    const int z = blockIdx.z, h = z & 7;
    const int i0 = blockIdx.y << 6, j0 = blockIdx.x << 6;
    const float* Q  = Qb + (long)z * 65536;
    const float* Kp = Kb + (long)z * 131072;
    const float* Rh = Rf + (long)h * 131072;
    float*       S  = Sb + (long)z * 524288;

    __shared__ __align__(16) char sraw[36864];
    float*    Qs = (float*)sraw;                 // 64 x 36 (raw fp32 q)
    uint32_t* Ks = (uint32_t*)(sraw + 9216);     // 64 x 36 [n][k] tf32
    uint32_t* Rs = (uint32_t*)(sraw + 18432);    // 128 x 36 [co][k] tf32
    float*    Gs = (float*)sraw;                 // 64 x 132 overlay (BD panel)
    __shared__ float u1s[128], u2s[128];

    const int tid = threadIdx.x, lane = tid & 31, wid = tid >> 5;
    const int wm = (wid & 3) << 4;          // row group 0/16/32/48
    const int wn = (wid >> 2) << 5;         // AC col group 0/32
    const int wc = (wid >> 2) << 6;         // BD col group 0/64
    const int g = lane >> 2, lt = lane & 3;

    if (tid < 128) { u1s[tid] = U1[(h << 7) + tid]; u2s[tid] = U2[(h << 7) + tid]; }

    const int cbase = 448 + j0 - i0;                   // in [0, 960]
    const int qm = tid >> 3, qk = (tid & 7) << 2;

    float4 acA[4], acB[8];
#pragma unroll
    for (int s = 0; s < 4; s++) acA[s] = make_float4(0.f, 0.f, 0.f, 0.f);
#pragma unroll
    for (int s = 0; s < 8; s++) acB[s] = make_float4(0.f, 0.f, 0.f, 0.f);

#pragma unroll
    for (int k0 = 0; k0 < 128; k0 += 32) {
        float4 tq[2]; uint4 tk[2], tr[4];
#pragma unroll
        for (int it = 0; it < 2; it++) {
            tq[it] = *(const float4*)(Q  + (long)(i0 + qm + (it << 5)) * 128 + k0 + qk);
            tk[it] = cvt4(*(const float4*)(Kp + (long)(j0 + qm + (it << 5)) * 128 + k0 + qk));
        }
#pragma unroll
        for (int it = 0; it < 4; it++) {
            int cr = cbase + qm + (it << 5);
            if (cr > 1023) cr = 1023;                  // clamped rows are masked anyway
            tr[it] = cvt4(*(const float4*)(Rh + (long)cr * 128 + k0 + qk));
        }
        __syncthreads();
#pragma unroll
        for (int it = 0; it < 2; it++) {
            *(float4*)&Qs[(qm + (it << 5)) * 36 + qk] = tq[it];
            *(uint4*)&Ks[(qm + (it << 5)) * 36 + qk] = tk[it];
        }
#pragma unroll
        for (int it = 0; it < 4; it++)
            *(uint4*)&Rs[(qm + (it << 5)) * 36 + qk] = tr[it];
        __syncthreads();
#pragma unroll
        for (int kk = 0; kk < 4; kk++) {
            const int kb = kk << 3;
            const int r0 = wm + g;
            float q0 = Qs[r0 * 36 + kb + lt];
            float q1 = Qs[(r0 + 8) * 36 + kb + lt];
            float q2 = Qs[r0 * 36 + kb + lt + 4];
            float q3 = Qs[(r0 + 8) * 36 + kb + lt + 4];
            float uA = u1s[k0 + kb + lt], uB = u1s[k0 + kb + lt + 4];
            uint32_t a1[4] = { f2tf(q0 + uA), f2tf(q1 + uA), f2tf(q2 + uB), f2tf(q3 + uB) };
            uA = u2s[k0 + kb + lt]; uB = u2s[k0 + kb + lt + 4];
            uint32_t a2[4] = { f2tf(q0 + uA), f2tf(q1 + uA), f2tf(q2 + uB), f2tf(q3 + uB) };
#pragma unroll
            for (int s = 0; s < 4; s++) {
                int n = wn + (s << 3) + g;
                mma8(acA[s], a1, Ks[n * 36 + kb + lt], Ks[n * 36 + kb + lt + 4]);
            }
#pragma unroll
            for (int s = 0; s < 8; s++) {
                int n = wc + (s << 3) + g;
                mma8(acB[s], a2, Rs[n * 36 + kb + lt], Rs[n * 36 + kb + lt + 4]);
            }
        }
    }

    __syncthreads();                 // all warps done reading Qs/Ks/Rs before overlay
    {
        int r = wm + g;
#pragma unroll
        for (int s = 0; s < 8; s++) {
            int c = wc + (s << 3) + (lt << 1);
            *(float2*)&Gs[r * 132 + c]       = make_float2(acB[s].x, acB[s].y);
            *(float2*)&Gs[(r + 8) * 132 + c] = make_float2(acB[s].z, acB[s].w);
        }
    }
    __syncthreads();

    const float inv = 0.08838834764831845f;   // 1/sqrt(128)
#pragma unroll
    for (int s = 0; s < 4; s++) {
        int rl0 = wm + g;
        int cl  = wn + (s << 3) + (lt << 1);
        float vals[4] = { acA[s].x, acA[s].y, acA[s].z, acA[s].w };
#pragma unroll
        for (int e = 0; e < 4; e++) {
            int rl = rl0 + ((e >> 1) << 3);
            int c  = cl + (e & 1);
            int i = i0 + rl, j = j0 + c;
            if (j <= i + 512) {
                S[(long)i * 1024 + j] = (vals[e] + Gs[rl * 132 + 63 + c - rl]) * inv;
            }
        }
    }
}

// ---------------- causal softmax (valid width = i+513) ----------------
__global__ __launch_bounds__(256) void softmax_kernel(float* __restrict__ S)
{
    const int row  = (blockIdx.x << 3) + (threadIdx.x >> 5);
    const int lane = threadIdx.x & 31;
    const int i = row & 511;
    const int valid = i + 513;
    float* p = S + (long)row * 1024;

    float4 v[8];
    float mx = -3.402823466e38f;
#pragma unroll
    for (int c2 = 0; c2 < 8; c2++) {
        int jb = (c2 << 7) + (lane << 2);
        v[c2] = *(const float4*)(p + jb);
        if (jb + 0 < valid) mx = fmaxf(mx, v[c2].x);
        if (jb + 1 < valid) mx = fmaxf(mx, v[c2].y);
        if (jb + 2 < valid) mx = fmaxf(mx, v[c2].z);
        if (jb + 3 < valid) mx = fmaxf(mx, v[c2].w);
    }
#pragma unroll
    for (int o = 16; o > 0; o >>= 1) mx = fmaxf(mx, __shfl_xor_sync(0xffffffffu, mx, o));

    float sum = 0.f;
#pragma unroll
    for (int c2 = 0; c2 < 8; c2++) {
        int jb = (c2 << 7) + (lane << 2);
        float e0 = (jb + 0 < valid) ? __expf(v[c2].x - mx) : 0.f;
        float e1 = (jb + 1 < valid) ? __expf(v[c2].y - mx) : 0.f;
        float e2 = (jb + 2 < valid) ? __expf(v[c2].z - mx) : 0.f;
        float e3 = (jb + 3 < valid) ? __expf(v[c2].w - mx) : 0.f;
        v[c2].x = e0; v[c2].y = e1; v[c2].z = e2; v[c2].w = e3;
        sum += e0 + e1 + e2 + e3;
    }
#pragma unroll
    for (int o = 16; o > 0; o >>= 1) sum += __shfl_xor_sync(0xffffffffu, sum, o);
    float rs = 1.0f / sum;
#pragma unroll
    for (int c2 = 0; c2 < 8; c2++) {
        int jb = (c2 << 7) + (lane << 2);
        v[c2].x *= rs; v[c2].y *= rs; v[c2].z *= rs; v[c2].w *= rs;
        *(float4*)(p + jb) = v[c2];
    }
}

// ---------------- LayerNorm over last dim (128) ----------------
__global__ __launch_bounds__(256) void ln_kernel(
    const float* __restrict__ Y, const float* __restrict__ gamma,
    const float* __restrict__ beta, float* __restrict__ out)
{
    const int row  = (blockIdx.x << 3) + (threadIdx.x >> 5);
    const int lane = threadIdx.x & 31;
    const float* y = Y + (long)row * 128;

    float4 v = *(const float4*)(y + (lane << 2));
    float s = v.x + v.y + v.z + v.w;
#pragma unroll
    for (int o = 16; o > 0; o >>= 1) s += __shfl_xor_sync(0xffffffffu, s, o);
    float mu = s * (1.0f / 128.0f);

    float dx = v.x - mu, dy = v.y - mu, dz = v.z - mu, dw = v.w - mu;
    float q = dx * dx + dy * dy + dz * dz + dw * dw;
#pragma unroll
    for (int o = 16; o > 0; o >>= 1) q += __shfl_xor_sync(0xffffffffu, q, o);
    float inv = rsqrtf(q * (1.0f / 128.0f) + 1e-5f);

    float4 g  = *(const float4*)(gamma + (lane << 2));
    float4 b4 = *(const float4*)(beta + (lane << 2));
    float4 o4;
    o4.x = dx * inv * g.x + b4.x;
    o4.y = dy * inv * g.y + b4.y;
    o4.z = dz * inv * g.z + b4.z;
    o4.w = dw * inv * g.w + b4.w;
    *(float4*)(out + (long)row * 128 + (lane << 2)) = o4;
}

// ---------------- launch ----------------
extern "C" void kernel_launch(void* const* d_in, const int* in_sizes, int n_in,
                              void* d_out, int out_size)
{
    const float* x     = (const float*)d_in[0];
    const float* mem   = (const float*)d_in[1];
    const float* R     = (const float*)d_in[2];
    // d_in[3] = att_mask (all ones; unused by reference)
    const float* u1    = (const float*)d_in[4];
    const float* u2    = (const float*)d_in[5];
    const float* Wq    = (const float*)d_in[6];
    const float* Wkv   = (const float*)d_in[7];
    const float* Wr    = (const float*)d_in[8];
    const float* Wmlp  = (const float*)d_in[9];
    const float* gamma = (const float*)d_in[10];
    const float* beta  = (const float*)d_in[11];
    float* out = (float*)d_out;

    float *hb, *qf, *kvf, *rf, *sb, *att, *yb;
    cudaGetSymbolAddress((void**)&hb,  g_h);
    cudaGetSymbolAddress((void**)&qf,  g_qf);
    cudaGetSymbolAddress((void**)&kvf, g_kvf);
    cudaGetSymbolAddress((void**)&rf,  g_rf);
    cudaGetSymbolAddress((void**)&sb,  g_s);
    cudaGetSymbolAddress((void**)&att, g_att);
    cudaGetSymbolAddress((void**)&yb,  g_y);

    // 1) h = concat(mem, x)
    concat_kernel<<<2048, 256>>>(x, mem, hb);
    // 2) qf = x @ Wq            (8192 x 1024, K=128)
    gemm_tf32<<<dim3(8, 64, 1), 256>>>(x, Wq, qf, 8192, 1024, 128, 0, 0, 0, nullptr);
    // 3) kvf = h @ Wkv          (16384 x 2048, K=128)
    gemm_tf32<<<dim3(16, 128, 1), 256>>>(hb, Wkv, kvf, 16384, 2048, 128, 0, 0, 0, nullptr);
    // 4) rf = R @ Wr            (1024 x 1024, K=128)
    gemm_tf32<<<dim3(8, 8, 1), 256>>>(R, Wr, rf, 1024, 1024, 128, 0, 0, 0, nullptr);
    // 5) S = ((q+u1)@k^T + circulant((q+u2)@r^T)) / sqrt(d), causal band only
    score_tf32<<<dim3(16, 8, 128), 256>>>(qf, kvf, rf, u1, u2, sb);
    // 6) P = softmax(S) with analytic causal mask
    softmax_kernel<<<8192, 256>>>(sb);
    // 7) att = P @ V            per (b,h): 512 x 128, K=1024 (V = second half of kvf)
    gemm_tf32<<<dim3(1, 4, 128), 256>>>(sb, kvf + 16777216L, att,
                                        512, 128, 1024, 524288L, 131072L, 65536L, nullptr);
    // 8) y = att @ Wmlp + x     (8192 x 128, K=1024)
    gemm_tf32<<<dim3(1, 64, 1), 256>>>(att, Wmlp, yb, 8192, 128, 1024, 0, 0, 0, x);
    // 9) out = LayerNorm(y) * gamma + beta
    ln_kernel<<<1024, 256>>>(yb, gamma, beta, out);
}